// round 7
// baseline (speedup 1.0000x reference)
#include <cuda_runtime.h>
#include <math.h>

#define Bv  4
#define Nn  24
#define NTT 16
#define TSS 48
#define TT  64
#define THR 384
#define NL  (Nn - 1)          // 23 l-slots per batch
#define SNAN 0x7fc00000u      // Ssc "not ready" sentinel

// ---------------- device scratch ----------------
__device__ __align__(16) float d_E0t [Bv][Nn][NTT][NTT][NTT];  // exp(R0) as [b][h][s][c][a]
__device__ __align__(16) float d_E1t [Bv][Nn][NTT][NTT][NTT];
__device__ float d_U0t [Bv][Nn][Nn][NTT][NTT];       // [b][h][k][s][a]
__device__ float d_U1t [Bv][Nn][Nn][NTT][NTT];       // [b][h][k][c][a]
__device__ float d_V0t [Bv][Nn][TT][NTT];            // [b][h][c][a]
__device__ float d_V1t [Bv][Nn][TT][NTT];            // [b][h][s][a]
__device__ float d_beta [Bv][Nn+1][Nn+1][NTT][Nn];
__device__ float d_betau[Bv][Nn+1][Nn+1][NTT];
__device__ float d_Ssc  [Bv][Nn+1][Nn+1];

// ---------------- kernel 1: rule precompute + Ssc sentinel fill ----------------
__global__ void __launch_bounds__(256) k_pre(const float* __restrict__ rule,
                                             const float* __restrict__ unary) {
    int blk = blockIdx.x;
    int h = blk % Nn;
    int a = (blk / Nn) % NTT;
    int b = blk / (Nn * NTT);
    const float2* R2 = (const float2*)(rule + (size_t)((b * NTT + a) * Nn + h) * (TT * TT * 2));

    __shared__ float Er0[TT][TT];
    __shared__ float Er1[TT][TT];
    __shared__ float eus[Nn][49];
    int tid = threadIdx.x;

    if (blk == 0) {  // sentinel-fill Ssc (doubles as dataflow flag); stream-ordered before k_chart
        for (int i = tid; i < Bv * (Nn + 1) * (Nn + 1); i += 256)
            ((unsigned*)&d_Ssc[0][0][0])[i] = SNAN;
    }

    for (int e = tid; e < TT * TT; e += 256) {
        float2 v = R2[e];
        int s = e >> 6, c = e & 63;
        Er0[s][c] = __expf(v.x);
        Er1[s][c] = __expf(v.y);
    }
    for (int t = tid; t < Nn * TSS; t += 256) {
        int k = t / TSS, c = t % TSS;
        eus[k][c] = __expf(unary[(b * Nn + k) * TT + NTT + c]);
    }
    __syncthreads();

    {
        int s = tid >> 4, c = tid & 15;
        d_E0t[b][h][s][c][a] = Er0[s][c];
        d_E1t[b][h][s][c][a] = Er1[s][c];
    }
    if (tid < 128) {
        int x = tid & 63;
        float acc = 0.f;
        if (tid < 64) {
            #pragma unroll 8
            for (int s = NTT; s < TT; s++) acc += Er0[s][x];
            d_V0t[b][h][x][a] = acc;
        } else {
            #pragma unroll 8
            for (int c = NTT; c < TT; c++) acc += Er1[x][c];
            d_V1t[b][h][x][a] = acc;
        }
    }
    if (tid < 192) {
        int which = tid / 96;
        int g = tid % 96;
        int x = g & 15, k0 = (g >> 4) * 4;
        float a0 = 0.f, a1 = 0.f, a2 = 0.f, a3 = 0.f;
        if (which == 0) {
            #pragma unroll 8
            for (int c = 0; c < TSS; c++) {
                float e = Er0[x][NTT + c];
                a0 += e * eus[k0 + 0][c];
                a1 += e * eus[k0 + 1][c];
                a2 += e * eus[k0 + 2][c];
                a3 += e * eus[k0 + 3][c];
            }
            d_U0t[b][h][k0 + 0][x][a] = a0;
            d_U0t[b][h][k0 + 1][x][a] = a1;
            d_U0t[b][h][k0 + 2][x][a] = a2;
            d_U0t[b][h][k0 + 3][x][a] = a3;
        } else {
            #pragma unroll 8
            for (int s = 0; s < TSS; s++) {
                float e = Er1[NTT + s][x];
                a0 += e * eus[k0 + 0][s];
                a1 += e * eus[k0 + 1][s];
                a2 += e * eus[k0 + 2][s];
                a3 += e * eus[k0 + 3][s];
            }
            d_U1t[b][h][k0 + 0][x][a] = a0;
            d_U1t[b][h][k0 + 1][x][a] = a1;
            d_U1t[b][h][k0 + 2][x][a] = a2;
            d_U1t[b][h][k0 + 3][x][a] = a3;
        }
    }
}

// spin until Ssc value is published (not sentinel); integer compare = fast-math safe
__device__ __forceinline__ float spin_ssc(const float* p, bool sleep) {
    float v = *(volatile const float*)p;
    while (__float_as_uint(v) == SNAN) {
        if (sleep) __nanosleep(20);
        v = *(volatile const float*)p;
    }
    return v;
}

// ---------------- kernel 2: dataflow chart kernel (deferred last child) ----------------
__global__ void __launch_bounds__(THR, 1) k_chart(const float* __restrict__ unary,
                                                  const float* __restrict__ root,
                                                  float* __restrict__ out) {
    extern __shared__ float dyn[];
    float* Psm  = dyn;                 // 2*256*25 = 12800 floats
    float* ownB = dyn + 12800;         // [23][16][24] = 8832 floats, slot = width-2
    __shared__ float eu_s[Nn][TT];
    __shared__ float buR[Nn][NTT];
    __shared__ float buL[Nn][NTT];
    __shared__ __align__(16) float wRT0[NTT][24];
    __shared__ __align__(16) float wRT1[NTT][24];
    __shared__ float BL2s[NTT][Nn];
    __shared__ float tmpsm[NTT][Nn];
    __shared__ float ownBu[Nn][NTT];   // slot = width-2
    __shared__ float ownS[Nn + 1];     // own Ssc by width
    __shared__ float wspe[Nn];
    __shared__ float buR0s[NTT];
    __shared__ float red[12];
    __shared__ float sref1_s, ssum0_s, Msm_s;

    int tid = threadIdx.x;
    int b = blockIdx.x / NL;
    int l = blockIdx.x % NL;

    for (int t = tid; t < Nn * TT; t += THR)
        (&eu_s[0][0])[t] = __expf(unary[b * Nn * TT + t]);
    for (int t = tid; t < 8832; t += THR) ownB[t] = 0.f;
    __syncthreads();

    int Wmax = Nn - l;
    for (int W = 2; W <= Wmax; W++) {
        int r = l + W;
        int nT = NTT * W;
        int Wp = W | 1;
        float tval1 = 0.f;
        int a = tid & 15, hh = tid >> 4;     // (a, hh) role for boundary/commit threads
        float u1v[16], v0v[16];

        if (W >= 3) {
            // ---- phase A: scale gather in warp 0 (spin on all but the LAST child) ----
            if (tid < 32) {
                int j = tid;
                float v = -1e30f;
                if (j >= 1 && j <= W - 2) {
                    float sl = ownS[j + 1];                 // Ssc[l][l+1+j]
                    float sr = 0.f;
                    if (j <= W - 3) sr = spin_ssc(&d_Ssc[b][l + 1 + j][r], true);
                    v = sl + sr;
                }
                __threadfence();   // acquire for the spun cells
                float mx = v;
                #pragma unroll
                for (int o = 16; o > 0; o >>= 1) mx = fmaxf(mx, __shfl_xor_sync(0xffffffffu, mx, o));
                if (j >= 1 && j <= W - 2) wspe[j] = expf(v - mx);
                if (j == 0) sref1_s = mx;
            }
            __syncthreads();

            // ---- children into smem (right: remote betau; left: own smem) ----
            if (tid < (W - 3) * NTT) {
                int j = (tid >> 4) + 1, c = tid & 15;
                buR[j][c] = wspe[j] * __ldcg(&d_betau[b][l + 1 + j][r][c]);
            }
            if (tid < (W - 2) * NTT) {
                int j = (tid >> 4) + 1, c = tid & 15;
                buL[j][c] = wspe[j] * ownBu[j - 1][c];
            }
            __syncthreads();
        }

        if (W >= 4) {
            // ---- transposed zero-padded weight tables (jj = j-1, j in [1, W-3]) ----
            for (int t = tid; t < NTT * 24; t += THR) {
                int c = t / 24, jj = t % 24;
                int j = jj + 1;
                bool in = (j <= W - 3);
                wRT0[c][jj] = in ? buR[j][c] : 0.f;
                wRT1[c][jj] = in ? buL[j][c] : 0.f;
            }
            __syncthreads();

            // ---- P build: betas upfront (own from smem, remote from L2), c-outer FMA ----
            if (tid < nT) {
                int phh = tid % W, x = tid / W;
                float bvL[24], bvR[24];
                #pragma unroll
                for (int k = 0; k < 24; k++) { bvL[k] = 0.f; bvR[k] = 0.f; }
                #pragma unroll
                for (int j = 1; j <= 21; j++) {
                    if (j <= W - 3) {
                        bvL[j - 1] = ownB[(j - 1) * 384 + x * 24 + phh];
                        bvR[j - 1] = __ldcg(&d_beta[b][l + 1 + j][r][x][l + phh]);
                    }
                }
                float* P0 = Psm;
                float* P1 = Psm + 256 * Wp;
                #pragma unroll
                for (int c = 0; c < NTT; c++) {
                    float a0 = 0.f, a1 = 0.f;
                    #pragma unroll
                    for (int k = 0; k < 6; k++) {
                        if (4 * k <= W - 4) {   // warp-uniform
                            float4 w0 = *(const float4*)&wRT0[c][4 * k];
                            float4 w1 = *(const float4*)&wRT1[c][4 * k];
                            a0 = fmaf(bvL[4 * k + 0], w0.x, a0);
                            a0 = fmaf(bvL[4 * k + 1], w0.y, a0);
                            a0 = fmaf(bvL[4 * k + 2], w0.z, a0);
                            a0 = fmaf(bvL[4 * k + 3], w0.w, a0);
                            a1 = fmaf(bvR[4 * k + 0], w1.x, a1);
                            a1 = fmaf(bvR[4 * k + 1], w1.y, a1);
                            a1 = fmaf(bvR[4 * k + 2], w1.z, a1);
                            a1 = fmaf(bvR[4 * k + 3], w1.w, a1);
                        }
                    }
                    P0[(x * NTT + c) * Wp + phh] = a0;
                    P1[(c * NTT + x) * Wp + phh] = a1;
                }
            }
            __syncthreads();

            // ---- contraction: warp per hh, lanes = (sc_lo, a4) -> coalesced E loads ----
            {
                int wid = tid >> 5, lane = tid & 31;
                int sc_lo = lane >> 2, a4 = lane & 3;
                const float* P0 = Psm;
                const float* P1 = Psm + 256 * Wp;
                for (int chh = wid; chh < W; chh += 12) {
                    const float4* E0 = reinterpret_cast<const float4*>(d_E0t[b][l + chh][0][0]);
                    const float4* E1 = reinterpret_cast<const float4*>(d_E1t[b][l + chh][0][0]);
                    const float* p0 = P0 + chh;
                    const float* p1 = P1 + chh;
                    float4 s0 = make_float4(0.f, 0.f, 0.f, 0.f);
                    float4 s1 = make_float4(0.f, 0.f, 0.f, 0.f);
                    #pragma unroll 8
                    for (int sc0 = 0; sc0 < 256; sc0 += 8) {
                        int sc = sc0 + sc_lo;
                        float v0 = p0[sc * Wp];
                        float v1 = p1[sc * Wp];
                        float4 e0 = __ldg(E0 + sc * 4 + a4);
                        float4 e1 = __ldg(E1 + sc * 4 + a4);
                        s0.x = fmaf(v0, e0.x, s0.x); s0.y = fmaf(v0, e0.y, s0.y);
                        s0.z = fmaf(v0, e0.z, s0.z); s0.w = fmaf(v0, e0.w, s0.w);
                        s1.x = fmaf(v1, e1.x, s1.x); s1.y = fmaf(v1, e1.y, s1.y);
                        s1.z = fmaf(v1, e1.z, s1.z); s1.w = fmaf(v1, e1.w, s1.w);
                    }
                    float4 s;
                    s.x = s0.x + s1.x; s.y = s0.y + s1.y;
                    s.z = s0.z + s1.z; s.w = s0.w + s1.w;
                    #pragma unroll
                    for (int o = 4; o <= 16; o <<= 1) {
                        s.x += __shfl_xor_sync(0xffffffffu, s.x, o);
                        s.y += __shfl_xor_sync(0xffffffffu, s.y, o);
                        s.z += __shfl_xor_sync(0xffffffffu, s.z, o);
                        s.w += __shfl_xor_sync(0xffffffffu, s.w, o);
                    }
                    if (sc_lo == 0) {
                        tmpsm[a4 * 4 + 0][chh] = s.x;
                        tmpsm[a4 * 4 + 1][chh] = s.y;
                        tmpsm[a4 * 4 + 2][chh] = s.z;
                        tmpsm[a4 * 4 + 3][chh] = s.w;
                    }
                }
            }
            __syncthreads();
        }

        // ---- phase A boundary (no dependence on (l+1, r)) + deferred-row preloads ----
        if (W >= 3) {
            if (tid < nT) {
                if (W >= 4) tval1 = tmpsm[a][hh];
                float s3 = 0.f;
                #pragma unroll
                for (int c = 0; c < NTT; c++)
                    s3 += __ldg(&d_U0t[b][l + hh][r - 1][c][a]) * ownB[(W - 3) * 384 + c * 24 + hh];
                tval1 += wspe[W - 2] * s3;
                if (hh == W - 1) {
                    float s4 = 0.f;
                    #pragma unroll
                    for (int c = 0; c < NTT; c++)
                        s4 += __ldg(&d_V1t[b][r - 1][c][a]) * buL[W - 2][c];
                    tval1 += s4;
                }
                // preload the deferred rows now (hide L2 latency under the spin)
                #pragma unroll
                for (int c = 0; c < NTT; c++)
                    u1v[c] = __ldg(&d_U1t[b][l + hh][l][c][a]);
                if (hh == 0) {
                    #pragma unroll
                    for (int c = 0; c < NTT; c++)
                        v0v[c] = __ldg(&d_V0t[b][l][c][a]);
                }
            }

            // ---- phase B: wait for the LAST child, fold its terms in ----
            if (tid == 0) {
                ssum0_s = spin_ssc(&d_Ssc[b][l + 1][r], false);
                __threadfence();
            }
            __syncthreads();
            if (tid < nT) {
                int c2 = tid / W, h2 = tid % W;
                BL2s[c2][h2] = __ldcg(&d_beta[b][l + 1][r][c2][l + h2]);
            }
            if (tid < NTT) buR0s[tid] = __ldcg(&d_betau[b][l + 1][r][tid]);
            __syncthreads();
        }

        // ---- assemble final tval ----
        float tval = 0.f;
        if (tid < nT) {
            if (W >= 3) {
                float sref = fmaxf(sref1_s, ssum0_s);
                float e1 = expf(sref1_s - sref);
                float e0 = expf(ssum0_s - sref);
                float s2 = 0.f;
                #pragma unroll
                for (int c = 0; c < NTT; c++) s2 += u1v[c] * BL2s[c][hh];
                tval = tval1 * e1 + e0 * s2;
                if (hh == 0) {
                    float s1 = 0.f;
                    #pragma unroll
                    for (int c = 0; c < NTT; c++) s1 += v0v[c] * buR0s[c];
                    tval += e0 * s1;
                }
            } else {  // W == 2: both children width-1, no deps, scale 0
                if (hh == 0) {
                    #pragma unroll 8
                    for (int c = 0; c < TSS; c++)
                        tval += eu_s[l + 1][NTT + c] * __ldg(&d_V0t[b][l][NTT + c][a]);
                } else {
                    #pragma unroll 8
                    for (int c = 0; c < TSS; c++)
                        tval += eu_s[l][NTT + c] * __ldg(&d_V1t[b][l + 1][NTT + c][a]);
                }
            }
        }

        // ---- max, rescale, commit, publish (Ssc last = release flag) ----
        float vmax = 0.f;
        if (tid < nT) {
            tmpsm[a][hh] = tval;
            vmax = tval;
        }
        #pragma unroll
        for (int o = 16; o > 0; o >>= 1) vmax = fmaxf(vmax, __shfl_xor_sync(0xffffffffu, vmax, o));
        if ((tid & 31) == 0) red[tid >> 5] = vmax;
        __syncthreads();
        if (tid < 32) {
            float v = (tid < 12) ? red[tid] : 0.f;
            #pragma unroll
            for (int o = 8; o > 0; o >>= 1) v = fmaxf(v, __shfl_xor_sync(0xffffffffu, v, o));
            if (tid == 0) Msm_s = v;
        }
        __syncthreads();
        float invM = 1.f / Msm_s;
        {
            int ca = tid / Nn, habs = tid % Nn;   // THR == 16*24 exactly
            float v = 0.f;
            if (habs >= l && habs < r) {
                v = tmpsm[ca][habs - l] * invM;
                ownB[(W - 2) * 384 + ca * 24 + (habs - l)] = v;
            }
            __stcg(&d_beta[b][l][r][ca][habs], v);
        }
        if (tid < NTT) {
            float accu = 0.f;
            for (int h2 = 0; h2 < W; h2++)
                accu += tmpsm[tid][h2] * eu_s[l + h2][tid];
            float bu = accu * invM;
            __stcg(&d_betau[b][l][r][tid], bu);
            ownBu[W - 2][tid] = bu;
            if (W == Nn) {   // only block (b, 0): fused root reduction
                float v = bu * __expf(root[b * NTT + tid]);
                #pragma unroll
                for (int o = 8; o > 0; o >>= 1) v += __shfl_xor_sync(0xffffu, v, o);
                if (tid == 0) {
                    float sf = fmaxf(sref1_s, ssum0_s);
                    out[b] = sf + logf(Msm_s) + logf(v);
                }
            }
        }
        __threadfence();   // make beta/betau visible before Ssc (the flag)
        __syncthreads();
        if (tid == 0) {
            float sf = (W >= 3) ? fmaxf(sref1_s, ssum0_s) : 0.f;
            float ss = sf + logf(Msm_s);
            ownS[W] = ss;
            __stcg(&d_Ssc[b][l][r], ss);
        }
        __syncthreads();
    }
}

// ---------------- launch ----------------
extern "C" void kernel_launch(void* const* d_in, const int* in_sizes, int n_in,
                              void* d_out, int out_size) {
    const float* unary = nullptr;
    const float* rule  = nullptr;
    const float* root  = nullptr;
    for (int i = 0; i < n_in; i++) {
        if (in_sizes[i] == Bv * Nn * TT)                      unary = (const float*)d_in[i];
        else if (in_sizes[i] == Bv * NTT * Nn * TT * TT * 2)  rule  = (const float*)d_in[i];
        else if (in_sizes[i] == Bv * NTT)                     root  = (const float*)d_in[i];
    }

    int dynBytes = (2 * 256 * 25 + 23 * 16 * 24) * (int)sizeof(float);  // 86528
    cudaFuncSetAttribute(k_chart, cudaFuncAttributeMaxDynamicSharedMemorySize, dynBytes);

    k_pre<<<Bv * NTT * Nn, 256>>>(rule, unary);
    k_chart<<<Bv * NL, THR, dynBytes>>>(unary, root, (float*)d_out);
}

// round 8
// speedup vs baseline: 1.2197x; 1.2197x over previous
#include <cuda_runtime.h>
#include <cuda_fp16.h>
#include <math.h>

#define Bv  4
#define Nn  24
#define NTT 16
#define TSS 48
#define TT  64
#define THR 384
#define NL  (Nn - 1)          // 23 l-slots per batch
#define SNAN 0x7fc00000u      // Ssc "not ready" sentinel
#define ESCALE 4096.0f
#define EINV   (1.0f / 4096.0f)

// ---------------- device scratch ----------------
__device__ __align__(16) __half d_E0h[Bv][Nn][256][NTT];   // exp(R0)*4096 as [b][h][sc][a], fp16
__device__ __align__(16) __half d_E1h[Bv][Nn][256][NTT];
__device__ float d_U0t [Bv][Nn][Nn][NTT][NTT];       // [b][h][k][s][a]
__device__ float d_U1t [Bv][Nn][Nn][NTT][NTT];       // [b][h][k][c][a]
__device__ float d_V0t [Bv][Nn][TT][NTT];            // [b][h][c][a]
__device__ float d_V1t [Bv][Nn][TT][NTT];            // [b][h][s][a]
__device__ float d_beta [Bv][Nn+1][Nn+1][NTT][Nn];
__device__ float d_betau[Bv][Nn+1][Nn+1][NTT];
__device__ float d_Ssc  [Bv][Nn+1][Nn+1];

// ---------------- kernel 1: rule precompute + Ssc sentinel fill ----------------
__global__ void __launch_bounds__(256) k_pre(const float* __restrict__ rule,
                                             const float* __restrict__ unary) {
    int blk = blockIdx.x;
    int h = blk % Nn;
    int a = (blk / Nn) % NTT;
    int b = blk / (Nn * NTT);
    const float2* R2 = (const float2*)(rule + (size_t)((b * NTT + a) * Nn + h) * (TT * TT * 2));

    __shared__ float Er0[TT][TT];
    __shared__ float Er1[TT][TT];
    __shared__ float eus[Nn][49];
    int tid = threadIdx.x;

    if (blk == 0) {  // sentinel-fill Ssc (doubles as dataflow flag); stream-ordered before k_chart
        for (int i = tid; i < Bv * (Nn + 1) * (Nn + 1); i += 256)
            ((unsigned*)&d_Ssc[0][0][0])[i] = SNAN;
    }

    for (int e = tid; e < TT * TT; e += 256) {
        float2 v = R2[e];
        int s = e >> 6, c = e & 63;
        Er0[s][c] = __expf(v.x);
        Er1[s][c] = __expf(v.y);
    }
    for (int t = tid; t < Nn * TSS; t += 256) {
        int k = t / TSS, c = t % TSS;
        eus[k][c] = __expf(unary[(b * Nn + k) * TT + NTT + c]);
    }
    __syncthreads();

    // E tables: fp16, pre-scaled by ESCALE, layout [sc][a]
    {
        int s = tid >> 4, c = tid & 15;
        d_E0h[b][h][s * 16 + c][a] = __float2half_rn(Er0[s][c] * ESCALE);
        d_E1h[b][h][s * 16 + c][a] = __float2half_rn(Er1[s][c] * ESCALE);
    }
    if (tid < 128) {
        int x = tid & 63;
        float acc = 0.f;
        if (tid < 64) {
            #pragma unroll 8
            for (int s = NTT; s < TT; s++) acc += Er0[s][x];
            d_V0t[b][h][x][a] = acc;
        } else {
            #pragma unroll 8
            for (int c = NTT; c < TT; c++) acc += Er1[x][c];
            d_V1t[b][h][x][a] = acc;
        }
    }
    if (tid < 192) {
        int which = tid / 96;
        int g = tid % 96;
        int x = g & 15, k0 = (g >> 4) * 4;
        float a0 = 0.f, a1 = 0.f, a2 = 0.f, a3 = 0.f;
        if (which == 0) {
            #pragma unroll 8
            for (int c = 0; c < TSS; c++) {
                float e = Er0[x][NTT + c];
                a0 += e * eus[k0 + 0][c];
                a1 += e * eus[k0 + 1][c];
                a2 += e * eus[k0 + 2][c];
                a3 += e * eus[k0 + 3][c];
            }
            d_U0t[b][h][k0 + 0][x][a] = a0;
            d_U0t[b][h][k0 + 1][x][a] = a1;
            d_U0t[b][h][k0 + 2][x][a] = a2;
            d_U0t[b][h][k0 + 3][x][a] = a3;
        } else {
            #pragma unroll 8
            for (int s = 0; s < TSS; s++) {
                float e = Er1[NTT + s][x];
                a0 += e * eus[k0 + 0][s];
                a1 += e * eus[k0 + 1][s];
                a2 += e * eus[k0 + 2][s];
                a3 += e * eus[k0 + 3][s];
            }
            d_U1t[b][h][k0 + 0][x][a] = a0;
            d_U1t[b][h][k0 + 1][x][a] = a1;
            d_U1t[b][h][k0 + 2][x][a] = a2;
            d_U1t[b][h][k0 + 3][x][a] = a3;
        }
    }
}

// spin until Ssc value is published (not sentinel); integer compare = fast-math safe
__device__ __forceinline__ float spin_ssc(const float* p) {
    float v = *(volatile const float*)p;
    while (__float_as_uint(v) == SNAN) {
        __nanosleep(20);
        v = *(volatile const float*)p;
    }
    return v;
}

// ---------------- kernel 2: dataflow chart kernel ----------------
__global__ void __launch_bounds__(THR, 1) k_chart(const float* __restrict__ unary,
                                                  const float* __restrict__ root,
                                                  float* __restrict__ out) {
    extern __shared__ float dyn[];
    float* Psm  = dyn;                 // 2*256*25 = 12800 floats
    float* ownB = dyn + 12800;         // [23][16][24] = 8832 floats, slot = width-2
    __shared__ float eu_s[Nn][TT];
    __shared__ __align__(16) float wRT0[NTT][24];   // [c][jj], jj=j-1, j in 1..W-3, zero-padded
    __shared__ __align__(16) float wRT1[NTT][24];
    __shared__ float BL2s[NTT][Nn];
    __shared__ float tmpsm[NTT][Nn];
    __shared__ float ownBu[Nn][NTT];   // slot = width-2
    __shared__ float ownS[Nn + 1];     // own Ssc by width (ownS[1] = 0)
    __shared__ float wspe[Nn];
    __shared__ float buR0s[NTT];       // wspe[0] * betau(l+1, r)
    __shared__ float buLW[NTT];        // wspe[W-2] * ownBu(l, r-1)
    __shared__ float red[12];
    __shared__ float sref_s, Msm_s;

    int tid = threadIdx.x;
    int b = blockIdx.x / NL;
    int l = blockIdx.x % NL;

    for (int t = tid; t < Nn * TT; t += THR)
        (&eu_s[0][0])[t] = __expf(unary[b * Nn * TT + t]);
    for (int t = tid; t < 8832; t += THR) ownB[t] = 0.f;
    if (tid < 2) ownS[tid] = 0.f;
    __syncthreads();

    int Wmax = Nn - l;
    for (int W = 2; W <= Wmax; W++) {
        int r = l + W;
        int nT = NTT * W;
        int Wp = W | 1;
        int a = tid & 15, hh = tid >> 4;

        if (W >= 3) {
            // ---- phase 1: warp 0 spins on all right children, computes split weights ----
            if (tid < 32) {
                int j = tid;
                float v = -1e30f;
                if (j <= W - 2) {
                    float sl = (j == 0)     ? 0.f : ownS[j + 1];
                    float sr = (j == W - 2) ? 0.f : spin_ssc(&d_Ssc[b][l + 1 + j][r]);
                    v = sl + sr;
                }
                __threadfence();   // acquire for the spun cells
                float mx = v;
                #pragma unroll
                for (int o = 16; o > 0; o >>= 1) mx = fmaxf(mx, __shfl_xor_sync(0xffffffffu, mx, o));
                if (j <= W - 2) wspe[j] = expf(v - mx);
                if (j == 0) sref_s = mx;
            }
            __syncthreads();

            // ---- phase 2: child data into smem ----
            for (int t = tid; t < NTT * 24; t += THR) {
                int c = t / 24, jj = t % 24;
                int j = jj + 1;
                bool in = (j <= W - 3);
                wRT0[c][jj] = in ? wspe[j] * __ldcg(&d_betau[b][l + 1 + j][r][c]) : 0.f;
                wRT1[c][jj] = in ? wspe[j] * ownBu[j - 1][c] : 0.f;
            }
            if (tid < nT) {
                int c2 = tid / W, h2 = tid % W;
                BL2s[c2][h2] = __ldcg(&d_beta[b][l + 1][r][c2][l + h2]);
            }
            if (tid >= 352) {   // last warp: small vectors
                int c = tid - 352;
                if (c < NTT) {
                    buR0s[c] = wspe[0] * __ldcg(&d_betau[b][l + 1][r][c]);
                    buLW[c]  = wspe[W - 2] * ownBu[W - 3][c];
                }
            }
            __syncthreads();
        } else {
            if (tid == 0) sref_s = 0.f;
            __syncthreads();
        }

        if (W >= 4) {
            // ---- P build: betas upfront (own from smem, remote from L2), c-outer FMA ----
            if (tid < nT) {
                int phh = tid % W, x = tid / W;
                float bvL[24], bvR[24];
                #pragma unroll
                for (int k = 0; k < 24; k++) { bvL[k] = 0.f; bvR[k] = 0.f; }
                #pragma unroll
                for (int j = 1; j <= 21; j++) {
                    if (j <= W - 3) {
                        bvL[j - 1] = ownB[(j - 1) * 384 + x * 24 + phh];
                        bvR[j - 1] = __ldcg(&d_beta[b][l + 1 + j][r][x][l + phh]);
                    }
                }
                float* P0 = Psm;
                float* P1 = Psm + 256 * Wp;
                #pragma unroll
                for (int c = 0; c < NTT; c++) {
                    float a0 = 0.f, a1 = 0.f;
                    #pragma unroll
                    for (int k = 0; k < 6; k++) {
                        if (4 * k <= W - 4) {   // warp-uniform
                            float4 w0 = *(const float4*)&wRT0[c][4 * k];
                            float4 w1 = *(const float4*)&wRT1[c][4 * k];
                            a0 = fmaf(bvL[4 * k + 0], w0.x, a0);
                            a0 = fmaf(bvL[4 * k + 1], w0.y, a0);
                            a0 = fmaf(bvL[4 * k + 2], w0.z, a0);
                            a0 = fmaf(bvL[4 * k + 3], w0.w, a0);
                            a1 = fmaf(bvR[4 * k + 0], w1.x, a1);
                            a1 = fmaf(bvR[4 * k + 1], w1.y, a1);
                            a1 = fmaf(bvR[4 * k + 2], w1.z, a1);
                            a1 = fmaf(bvR[4 * k + 3], w1.w, a1);
                        }
                    }
                    P0[(x * NTT + c) * Wp + phh] = a0;
                    P1[(c * NTT + x) * Wp + phh] = a1;
                }
            }
            __syncthreads();

            // ---- contraction: warp per hh; lanes = (sc_lo 16, a8 2); fp16 E, fp32 accum ----
            {
                int wid = tid >> 5, lane = tid & 31;
                int sc_lo = lane >> 1, a8 = lane & 1;
                const float* P0 = Psm;
                const float* P1 = Psm + 256 * Wp;
                for (int chh = wid; chh < W; chh += 12) {
                    const uint4* E0 = reinterpret_cast<const uint4*>(&d_E0h[b][l + chh][0][0]);
                    const uint4* E1 = reinterpret_cast<const uint4*>(&d_E1h[b][l + chh][0][0]);
                    const float* p0 = P0 + chh;
                    const float* p1 = P1 + chh;
                    float acc[8];
                    #pragma unroll
                    for (int k = 0; k < 8; k++) acc[k] = 0.f;
                    #pragma unroll
                    for (int i = 0; i < 16; i++) {
                        int sc = i * 16 + sc_lo;
                        float v0 = p0[sc * Wp];
                        float v1 = p1[sc * Wp];
                        uint4 e0 = __ldg(E0 + sc * 2 + a8);
                        uint4 e1 = __ldg(E1 + sc * 2 + a8);
                        float2 f;
                        f = __half22float2(*reinterpret_cast<const __half2*>(&e0.x));
                        acc[0] = fmaf(v0, f.x, acc[0]); acc[1] = fmaf(v0, f.y, acc[1]);
                        f = __half22float2(*reinterpret_cast<const __half2*>(&e0.y));
                        acc[2] = fmaf(v0, f.x, acc[2]); acc[3] = fmaf(v0, f.y, acc[3]);
                        f = __half22float2(*reinterpret_cast<const __half2*>(&e0.z));
                        acc[4] = fmaf(v0, f.x, acc[4]); acc[5] = fmaf(v0, f.y, acc[5]);
                        f = __half22float2(*reinterpret_cast<const __half2*>(&e0.w));
                        acc[6] = fmaf(v0, f.x, acc[6]); acc[7] = fmaf(v0, f.y, acc[7]);
                        f = __half22float2(*reinterpret_cast<const __half2*>(&e1.x));
                        acc[0] = fmaf(v1, f.x, acc[0]); acc[1] = fmaf(v1, f.y, acc[1]);
                        f = __half22float2(*reinterpret_cast<const __half2*>(&e1.y));
                        acc[2] = fmaf(v1, f.x, acc[2]); acc[3] = fmaf(v1, f.y, acc[3]);
                        f = __half22float2(*reinterpret_cast<const __half2*>(&e1.z));
                        acc[4] = fmaf(v1, f.x, acc[4]); acc[5] = fmaf(v1, f.y, acc[5]);
                        f = __half22float2(*reinterpret_cast<const __half2*>(&e1.w));
                        acc[6] = fmaf(v1, f.x, acc[6]); acc[7] = fmaf(v1, f.y, acc[7]);
                    }
                    #pragma unroll
                    for (int o = 2; o <= 16; o <<= 1) {
                        #pragma unroll
                        for (int k = 0; k < 8; k++)
                            acc[k] += __shfl_xor_sync(0xffffffffu, acc[k], o);
                    }
                    if (sc_lo == 0) {
                        int abase = a8 * 8;
                        #pragma unroll
                        for (int k = 0; k < 8; k++)
                            tmpsm[abase + k][chh] = acc[k] * EINV;
                    }
                }
            }
            __syncthreads();
        }

        // ---- boundary terms + assemble tval ----
        float tval = 0.f;
        if (tid < nT) {
            if (W >= 3) {
                if (W >= 4) tval = tmpsm[a][hh];
                float s2 = 0.f, s3 = 0.f;
                #pragma unroll
                for (int c = 0; c < NTT; c++) {
                    s2 += __ldg(&d_U1t[b][l + hh][l][c][a]) * BL2s[c][hh];
                    s3 += __ldg(&d_U0t[b][l + hh][r - 1][c][a]) * ownB[(W - 3) * 384 + c * 24 + hh];
                }
                tval += wspe[0] * s2 + wspe[W - 2] * s3;
                if (hh == 0) {
                    float s1 = 0.f;
                    #pragma unroll
                    for (int c = 0; c < NTT; c++)
                        s1 += __ldg(&d_V0t[b][l][c][a]) * buR0s[c];
                    tval += s1;
                }
                if (hh == W - 1) {
                    float s4 = 0.f;
                    #pragma unroll
                    for (int c = 0; c < NTT; c++)
                        s4 += __ldg(&d_V1t[b][r - 1][c][a]) * buLW[c];
                    tval += s4;
                }
            } else {  // W == 2: both children width-1, scale 0
                if (hh == 0) {
                    #pragma unroll 8
                    for (int c = 0; c < TSS; c++)
                        tval += eu_s[l + 1][NTT + c] * __ldg(&d_V0t[b][l][NTT + c][a]);
                } else {
                    #pragma unroll 8
                    for (int c = 0; c < TSS; c++)
                        tval += eu_s[l][NTT + c] * __ldg(&d_V1t[b][l + 1][NTT + c][a]);
                }
            }
        }

        // ---- max, rescale, commit, publish (Ssc last = release flag) ----
        float vmax = 0.f;
        if (tid < nT) {
            tmpsm[a][hh] = tval;
            vmax = tval;
        }
        #pragma unroll
        for (int o = 16; o > 0; o >>= 1) vmax = fmaxf(vmax, __shfl_xor_sync(0xffffffffu, vmax, o));
        if ((tid & 31) == 0) red[tid >> 5] = vmax;
        __syncthreads();
        if (tid < 32) {
            float v = (tid < 12) ? red[tid] : 0.f;
            #pragma unroll
            for (int o = 8; o > 0; o >>= 1) v = fmaxf(v, __shfl_xor_sync(0xffffffffu, v, o));
            if (tid == 0) Msm_s = v;
        }
        __syncthreads();
        float invM = 1.f / Msm_s;
        {
            int ca = tid / Nn, habs = tid % Nn;   // THR == 16*24 exactly
            float v = 0.f;
            if (habs >= l && habs < r) {
                v = tmpsm[ca][habs - l] * invM;
                ownB[(W - 2) * 384 + ca * 24 + (habs - l)] = v;
            }
            __stcg(&d_beta[b][l][r][ca][habs], v);
        }
        if (tid < NTT) {
            float accu = 0.f;
            for (int h2 = 0; h2 < W; h2++)
                accu += tmpsm[tid][h2] * eu_s[l + h2][tid];
            float bu = accu * invM;
            __stcg(&d_betau[b][l][r][tid], bu);
            ownBu[W - 2][tid] = bu;
            if (W == Nn) {   // only block (b, 0): fused root reduction
                float v = bu * __expf(root[b * NTT + tid]);
                #pragma unroll
                for (int o = 8; o > 0; o >>= 1) v += __shfl_xor_sync(0xffffu, v, o);
                if (tid == 0) out[b] = sref_s + logf(Msm_s) + logf(v);
            }
        }
        __threadfence();   // make beta/betau visible before Ssc (the flag)
        __syncthreads();
        if (tid == 0) {
            float ss = sref_s + logf(Msm_s);
            ownS[W] = ss;
            __stcg(&d_Ssc[b][l][r], ss);
        }
        __syncthreads();
    }
}

// ---------------- launch ----------------
extern "C" void kernel_launch(void* const* d_in, const int* in_sizes, int n_in,
                              void* d_out, int out_size) {
    const float* unary = nullptr;
    const float* rule  = nullptr;
    const float* root  = nullptr;
    for (int i = 0; i < n_in; i++) {
        if (in_sizes[i] == Bv * Nn * TT)                      unary = (const float*)d_in[i];
        else if (in_sizes[i] == Bv * NTT * Nn * TT * TT * 2)  rule  = (const float*)d_in[i];
        else if (in_sizes[i] == Bv * NTT)                     root  = (const float*)d_in[i];
    }

    int dynBytes = (2 * 256 * 25 + 23 * 16 * 24) * (int)sizeof(float);  // 86528
    cudaFuncSetAttribute(k_chart, cudaFuncAttributeMaxDynamicSharedMemorySize, dynBytes);

    k_pre<<<Bv * NTT * Nn, 256>>>(rule, unary);
    k_chart<<<Bv * NL, THR, dynBytes>>>(unary, root, (float*)d_out);
}